// round 14
// baseline (speedup 1.0000x reference)
#include <cuda_runtime.h>
#include <math.h>

#define BATCH 64
#define NCLS  10
#define NDIR  4
#define CHW   16384     // C*H*W
#define FCHW  32768     // F*C*H*W, F=2
#define EPSV  1e-6f
#define NK    40        // NDIR*NCLS
#define TC    64        // chw positions per block
#define NBLK  (CHW/TC)  // 256 blocks
#define NTHR  128       // TC * 2 (f halves)

// ---------------- device scratch ----------------
__device__ float g_pnorm[NBLK * NK];   // per-block partial norm[d*10+c]
__device__ int   g_ctr;                // zero-init; last block resets to 0 (graph-replay safe)

// log_sigmoid, fast-math (args O(1))
__device__ __forceinline__ float lsig(float x) {
    return fminf(x, 0.f) - __logf(1.f + __expf(-fabsf(x)));
}

__global__ __launch_bounds__(NTHR) void k_all(
    const float* __restrict__ xle,
    const float* __restrict__ XLEs,
    const float* __restrict__ miu,
    const int*   __restrict__ labels,
    const float* __restrict__ w1,
    const float* __restrict__ tao,
    const float* __restrict__ weight,
    const float* __restrict__ sigmas,
    const float* __restrict__ Xw,
    float* __restrict__ out)
{
    __shared__ int   s_lab[BATCH], s_hist[NCLS], s_start[NCLS + 1], s_order[BATCH];
    __shared__ float s_inv[NCLS], s_rt[NK], s_rs[NK], s_w[NDIR];
    __shared__ float s_mt[NCLS][TC], s_lmm[NCLS][TC];   // means tables (shared-only!)
    __shared__ float s_red[NTHR + 2][NK + 1];           // stride-41 reduction tile
    __shared__ int   s_last;

    const int t = threadIdx.x;

    // ---- block-local tiny prep (labels sort + ratio tables) ----
    if (t < BATCH) s_lab[t] = labels[t];
    if (t < NCLS)  s_hist[t] = 0;
    if (t >= 64 && t < 64 + NK) {
        int k = t - 64, c = k >> 2, d = k & 3;
        float s2 = sigmas[c] * sigmas[c], t2 = tao[d] * tao[d];
        float inv = 1.f / (s2 + t2);
        s_rt[k] = t2 * inv; s_rs[k] = s2 * inv;
    }
    if (t >= 104 && t < 108) {
        int d = t - 104;
        float s = w1[0]*w1[0] + w1[1]*w1[1] + w1[2]*w1[2] + w1[3]*w1[3];
        s_w[d] = w1[d] * w1[d] / s;
    }
    __syncthreads();
    if (t < BATCH) atomicAdd(&s_hist[s_lab[t]], 1);
    __syncthreads();
    if (t == 0) {
        int p = 0;
        for (int c = 0; c < NCLS; c++) { s_start[c] = p; p += s_hist[c]; }
        s_start[NCLS] = p;
    }
    if (t < NCLS) s_inv[t] = 1.f / (Xw[t] + (float)s_hist[t]);
    __syncthreads();
    if (t < BATCH) {                 // stable rank within class
        int lab = s_lab[t], r = 0;
        for (int j = 0; j < t; j++) r += (s_lab[j] == lab);
        s_order[s_start[lab] + r] = t;
    }
    __syncthreads();

    // ---- phase 1: segment means, norm partials, means tables ----
    const int i   = t & (TC - 1);
    const int f   = t >> 6;                       // 0 or 1
    const int chw = blockIdx.x * TC + i;
    const int idx = f * CHW + chw;                // flat (f,chw)

    float lsm[NDIR], lsme[NDIR], miu0[NDIR];
#pragma unroll
    for (int d = 0; d < NDIR; d++) {
        float m = miu[d * FCHW + idx];
        lsm[d] = lsig(m);
        if (f) { lsme[d] = lsig(m + EPSV); miu0[d] = miu[d * FCHW + chw]; }
    }

    float acc[NK];
#pragma unroll
    for (int k = 0; k < NK; k++) acc[k] = 0.f;

#pragma unroll
    for (int c = 0; c < NCLS; c++) {
        float s = 0.f;
        const int j1 = s_start[c + 1];
        for (int j = s_start[c]; j < j1; j++)
            s += xle[s_order[j] * FCHW + idx];
        const float xb = (XLEs[c * FCHW + idx] + s) * s_inv[c];
        const float lx = lsig(xb);
#pragma unroll
        for (int d = 0; d < NDIR; d++) {
            float df = lx - lsm[d];
            acc[d * NCLS + c] = fmaf(df, df, acc[d * NCLS + c]);
        }
        if (f) {   // means for this chw (mag = x_bins[c, f=1, chw] = xb)
            float lmag = lsig(xb + EPSV);
            float mm = 0.f, mt = 0.f;
#pragma unroll
            for (int d = 0; d < NDIR; d++) {
                float rt = s_rt[c * 4 + d], rs = s_rs[c * 4 + d], w = s_w[d];
                mm += __expf((rt * lmag + rs * lsme[d]) * w);
                mt += (xb * rt + miu0[d] * rs) * w;
            }
            s_mt[c][i]  = mt;
            s_lmm[c][i] = __logf(mm + EPSV);
        }
    }

    // ---- block reduce acc[40] -> per-block partial (deterministic) ----
#pragma unroll
    for (int k = 0; k < NK; k++) s_red[t][k] = acc[k];
    __syncthreads();
    if (t < 2 * NK) {                      // 80 threads: 2 half-partials each
        int p = t / NK, k = t - p * NK;
        float s0 = 0.f, s1 = 0.f;
        for (int r = p * 64; r < p * 64 + 64; r += 2) { s0 += s_red[r][k]; s1 += s_red[r + 1][k]; }
        s_red[NTHR + p][k] = s0 + s1;
    }
    __syncthreads();
    if (t < NK)
        g_pnorm[blockIdx.x * NK + t] = s_red[NTHR][t] + s_red[NTHR + 1][t];

    // ---- phase 2: outputs. means in registers, loop over batches (L1-hit re-reads) ----
    float mtreg[NCLS], lmreg[NCLS];
#pragma unroll
    for (int c = 0; c < NCLS; c++) { mtreg[c] = s_mt[c][i]; lmreg[c] = s_lmm[c][i]; }
    const float w0  = weight[0] * weight[0];
    const float w1s = weight[1] * weight[1];
    const int   b0  = t >> 6;
#pragma unroll 4
    for (int r = 0; r < 32; r++) {
        int b = b0 + 2 * r;
        float x0  = xle[b * FCHW + chw];
        float lx1 = __logf(xle[b * FCHW + CHW + chw]);
        float best = 3.402823466e38f;
#pragma unroll
        for (int c = 0; c < NCLS; c++)
            best = fminf(best, fmaf(w0, fabsf(x0 - mtreg[c]), w1s * fabsf(lx1 - lmreg[c])));
        out[b * CHW + chw] = best;
    }

    // ---- last block computes the loss (threadfence-reduction pattern) ----
    if (t == 0) {
        __threadfence();
        s_last = (atomicAdd(&g_ctr, 1) == NBLK - 1) ? 1 : 0;
    }
    __syncthreads();
    if (s_last) {
        __shared__ float sv[NK];
        if (t < NK) {
            float s = 0.f;
#pragma unroll 8
            for (int p = 0; p < NBLK; p++) s += g_pnorm[p * NK + t];
            int d = t / NCLS, c = t - d * NCLS;
            float t2 = tao[d] * tao[d], s2 = sigmas[c] * sigmas[c];
            float cnt = Xw[c] + (float)s_hist[c];
            float term1 = s2 / ((t2 + s2) * (t2 + s2));
            sv[t] = term1 * (s2 * s + 2.f * (float)CHW * (t2 * t2 - s2 * s2) / cnt);
        }
        __syncthreads();
        if (t < NDIR) {
            float s = 0.f;
#pragma unroll
            for (int c = 0; c < NCLS; c++) s += sv[t * NCLS + c];
            out[BATCH * CHW + t] = s * (1.f / NCLS);
        }
        if (t == 0) g_ctr = 0;   // reset for next graph replay
    }
}

extern "C" void kernel_launch(void* const* d_in, const int* in_sizes, int n_in,
                              void* d_out, int out_size) {
    const float* xle    = (const float*)d_in[0];   // x_LE    (64,2,64,16,16)
    const int*   labels = (const int*)  d_in[1];   // labels  (64,)
    const float* w1     = (const float*)d_in[2];   // w1      (4,)
    // d_in[3] = w2 (unused: reference computes w2n from w1)
    const float* miu    = (const float*)d_in[4];   // miu     (4,2,64,16,16)
    const float* tao    = (const float*)d_in[5];   // tao     (4,)
    const float* weight = (const float*)d_in[6];   // weight  (2,)
    const float* sigmas = (const float*)d_in[7];   // sigmas  (10,)
    const float* XLEs   = (const float*)d_in[8];   // X_LEs   (10,2,64,16,16)
    const float* Xw     = (const float*)d_in[9];   // X_weights (10,1)
    float* out = (float*)d_out;                    // [x_out (64*16384) | loss (4)]

    k_all<<<NBLK, NTHR>>>(xle, XLEs, miu, labels, w1, tao, weight, sigmas, Xw, out);
}

// round 16
// speedup vs baseline: 1.2179x; 1.2179x over previous
#include <cuda_runtime.h>
#include <math.h>

#define BATCH 64
#define NCLS  10
#define NDIR  4
#define CHW   16384     // C*H*W
#define FCHW  32768     // F*C*H*W, F=2
#define EPSV  1e-6f
#define NK    40        // NDIR*NCLS
#define TC    16        // chw positions per block
#define NBLK  (CHW/TC)  // 1024 blocks
#define NTHR  128

// ---------------- device scratch ----------------
__device__ float g_pnorm[NBLK * NK];   // per-block partial norm[d*10+c]
__device__ int   g_ctr;                // zero-init; last block resets (graph-replay safe)

// log_sigmoid, fast-math (args O(1))
__device__ __forceinline__ float lsig(float x) {
    return fminf(x, 0.f) - __logf(1.f + __expf(-fabsf(x)));
}

__global__ __launch_bounds__(NTHR) void k_all(
    const float* __restrict__ xle,
    const float* __restrict__ XLEs,
    const float* __restrict__ miu,
    const int*   __restrict__ labels,
    const float* __restrict__ w1,
    const float* __restrict__ tao,
    const float* __restrict__ weight,
    const float* __restrict__ sigmas,
    const float* __restrict__ Xw,
    float* __restrict__ out)
{
    __shared__ int   s_lab[BATCH], s_hist[NCLS], s_start[NCLS + 1], s_ord[BATCH];
    __shared__ float s_inv[NCLS], s_rt[NK], s_rs[NK], s_w[NDIR];
    __shared__ float s_lsm[NDIR][32];     // lsig(miu[d, slot])  (slot = f*16+ci)
    __shared__ float s_lsme[NDIR][TC];    // lsig(miu[d,1,ci]+eps)
    __shared__ float s_miu0[NDIR][TC];    // miu[d,0,ci]
    __shared__ float s_mt[NCLS][TC], s_lmm[NCLS][TC];
    __shared__ float s_nred[NK * 33];     // padded norm tile (also reused for sv)
    __shared__ float s_q[3][NK];
    __shared__ int   s_last;

    const int t    = threadIdx.x;
    const int base = blockIdx.x * TC;

    // ---- tiny prep: labels sort + ratio tables + miu tables ----
    if (t < BATCH) s_lab[t] = labels[t];
    if (t < NCLS)  s_hist[t] = 0;
    if (t >= 64 && t < 64 + NK) {
        int k = t - 64, c = k >> 2, d = k & 3;
        float s2 = sigmas[c] * sigmas[c], t2 = tao[d] * tao[d];
        float inv = 1.f / (s2 + t2);
        s_rt[k] = t2 * inv; s_rs[k] = s2 * inv;
    }
    if (t >= 104 && t < 108) {
        int d = t - 104;
        float s = w1[0]*w1[0] + w1[1]*w1[1] + w1[2]*w1[2] + w1[3]*w1[3];
        s_w[d] = w1[d] * w1[d] / s;
    }
    {   // all 128 threads: one miu value each
        int d = t >> 5, slot = t & 31, ff = slot >> 4, ci = slot & 15;
        s_lsm[d][slot] = lsig(miu[d * FCHW + ff * CHW + base + ci]);
    }
    if (t < 64) {
        int d = t >> 4, ci = t & 15;
        s_lsme[d][ci] = lsig(miu[d * FCHW + CHW + base + ci] + EPSV);
        s_miu0[d][ci] = miu[d * FCHW + base + ci];
    }
    __syncthreads();
    if (t < BATCH) atomicAdd(&s_hist[s_lab[t]], 1);
    __syncthreads();
    if (t == 0) {
        int p = 0;
        for (int c = 0; c < NCLS; c++) { s_start[c] = p; p += s_hist[c]; }
        s_start[NCLS] = p;
    }
    if (t < NCLS) s_inv[t] = 1.f / (Xw[t] + (float)s_hist[t]);
    __syncthreads();
    if (t < BATCH) {                 // stable rank within class
        int lab = s_lab[t], r = 0;
        for (int j = 0; j < t; j++) r += (s_lab[j] == lab);
        s_ord[s_start[lab] + r] = t;
    }
    __syncthreads();

    // ---- phase 1: warp g owns classes {g, g+4, g+8}; lanes = 32 (f,chw) slots ----
    const int slot = t & 31, g = t >> 5;
    const int ff = slot >> 4, ci = slot & 15;
    const int idx = ff * CHW + base + ci;

    for (int c = g; c < NCLS; c += 4) {
        float s = 0.f;
        const int j1 = s_start[c + 1];
        for (int j = s_start[c]; j < j1; j++)
            s += xle[s_ord[j] * FCHW + idx];           // coalesced across lanes
        const float xb = (XLEs[c * FCHW + idx] + s) * s_inv[c];
        const float lx = lsig(xb);
#pragma unroll
        for (int d = 0; d < NDIR; d++) {
            float df = lx - s_lsm[d][slot];
            s_nred[(d * NCLS + c) * 33 + slot] = df * df;
        }
        if (ff) {   // means from x_bins[c, f=1, chw] = xb
            float lmag = lsig(xb + EPSV);
            float mm = 0.f, mt = 0.f;
#pragma unroll
            for (int d = 0; d < NDIR; d++) {
                float rt = s_rt[c * 4 + d], rs = s_rs[c * 4 + d], w = s_w[d];
                mm += __expf((rt * lmag + rs * s_lsme[d][ci]) * w);
                mt += (xb * rt + s_miu0[d][ci] * rs) * w;
            }
            s_mt[c][ci]  = mt;
            s_lmm[c][ci] = __logf(mm + EPSV);
        }
    }
    __syncthreads();

    // ---- per-block norm partial (deterministic, conflict-free via pad-33) ----
    if (t < NK) {
        float s = 0.f;
#pragma unroll
        for (int sl = 0; sl < 32; sl++) s += s_nred[t * 33 + sl];
        g_pnorm[blockIdx.x * NK + t] = s;
    }

    // ---- phase 2: outputs; means in registers, x_LE re-reads are L1-hot ----
    const int ci2 = t & 15, brow = t >> 4;
    float mtreg[NCLS], lmreg[NCLS];
#pragma unroll
    for (int c = 0; c < NCLS; c++) { mtreg[c] = s_mt[c][ci2]; lmreg[c] = s_lmm[c][ci2]; }
    const float w0  = weight[0] * weight[0];
    const float w1s = weight[1] * weight[1];
#pragma unroll
    for (int r = 0; r < 8; r++) {
        int b = r * 8 + brow;
        float x0  = xle[b * FCHW + base + ci2];
        float lx1 = __logf(xle[b * FCHW + CHW + base + ci2]);
        float best = 3.402823466e38f;
#pragma unroll
        for (int c = 0; c < NCLS; c++)
            best = fminf(best, fmaf(w0, fabsf(x0 - mtreg[c]), w1s * fabsf(lx1 - lmreg[c])));
        out[b * CHW + base + ci2] = best;
    }

    // ---- loss in last-finished block ----
    __threadfence();
    __syncthreads();
    if (t == 0) s_last = (atomicAdd(&g_ctr, 1) == NBLK - 1) ? 1 : 0;
    __syncthreads();
    if (s_last) {
        if (t < 120) {               // 3 partials x 40 k, dual accumulators
            int k = t % NK, part = t / NK;
            float a0 = 0.f, a1 = 0.f;
            int p = part;
            for (; p + 3 < NBLK; p += 6) {
                a0 += g_pnorm[p * NK + k];
                a1 += g_pnorm[(p + 3) * NK + k];
            }
            if (p < NBLK) a0 += g_pnorm[p * NK + k];
            s_q[part][k] = a0 + a1;
        }
        __syncthreads();
        if (t < NK) {
            float nrm = s_q[0][t] + s_q[1][t] + s_q[2][t];
            int d = t / NCLS, c = t - d * NCLS;
            float t2 = tao[d] * tao[d], s2 = sigmas[c] * sigmas[c];
            float cnt = Xw[c] + (float)s_hist[c];
            float term1 = s2 / ((t2 + s2) * (t2 + s2));
            s_nred[t] = term1 * (s2 * nrm + 2.f * (float)CHW * (t2 * t2 - s2 * s2) / cnt);
        }
        __syncthreads();
        if (t < NDIR) {
            float s = 0.f;
#pragma unroll
            for (int c = 0; c < NCLS; c++) s += s_nred[t * NCLS + c];
            out[BATCH * CHW + t] = s * (1.f / NCLS);
        }
        if (t == 0) g_ctr = 0;      // reset for next graph replay
    }
}

extern "C" void kernel_launch(void* const* d_in, const int* in_sizes, int n_in,
                              void* d_out, int out_size) {
    const float* xle    = (const float*)d_in[0];   // x_LE    (64,2,64,16,16)
    const int*   labels = (const int*)  d_in[1];   // labels  (64,)
    const float* w1     = (const float*)d_in[2];   // w1      (4,)
    // d_in[3] = w2 (unused: reference computes w2n from w1)
    const float* miu    = (const float*)d_in[4];   // miu     (4,2,64,16,16)
    const float* tao    = (const float*)d_in[5];   // tao     (4,)
    const float* weight = (const float*)d_in[6];   // weight  (2,)
    const float* sigmas = (const float*)d_in[7];   // sigmas  (10,)
    const float* XLEs   = (const float*)d_in[8];   // X_LEs   (10,2,64,16,16)
    const float* Xw     = (const float*)d_in[9];   // X_weights (10,1)
    float* out = (float*)d_out;                    // [x_out (64*16384) | loss (4)]

    k_all<<<NBLK, NTHR>>>(xle, XLEs, miu, labels, w1, tao, weight, sigmas, Xw, out);
}

// round 17
// speedup vs baseline: 1.4818x; 1.2166x over previous
#include <cuda_runtime.h>
#include <math.h>

#define BATCH 64
#define NCLS  10
#define NDIR  4
#define CHW   16384     // C*H*W
#define FCHW  32768     // F*C*H*W, F=2
#define EPSV  1e-6f
#define NK    40        // NDIR*NCLS
#define TC    16        // chw positions per block
#define NBLK  (CHW/TC)  // 1024 blocks
#define NTHR  256       // 8 warps

// ---------------- device scratch ----------------
__device__ float g_norm[NK];   // zero-init; atomically accumulated; last block resets
__device__ int   g_ctr;        // zero-init; last block resets (graph-replay safe)

// log_sigmoid, fast-math (args O(1))
__device__ __forceinline__ float lsig(float x) {
    return fminf(x, 0.f) - __logf(1.f + __expf(-fabsf(x)));
}

__global__ __launch_bounds__(NTHR, 6) void k_all(
    const float* __restrict__ xle,
    const float* __restrict__ XLEs,
    const float* __restrict__ miu,
    const int*   __restrict__ labels,
    const float* __restrict__ w1,
    const float* __restrict__ tao,
    const float* __restrict__ weight,
    const float* __restrict__ sigmas,
    const float* __restrict__ Xw,
    float* __restrict__ out)
{
    __shared__ int   s_lab[BATCH], s_hist[NCLS], s_start[NCLS + 1], s_ord[BATCH];
    __shared__ float s_inv[NCLS], s_rt[NK], s_rs[NK], s_w[NDIR];
    __shared__ float s_lsm[NDIR][32];     // lsig(miu[d, slot])  (slot = f*16+ci)
    __shared__ float s_lsme[NDIR][TC];    // lsig(miu[d,1,ci]+eps)
    __shared__ float s_miu0[NDIR][TC];    // miu[d,0,ci]
    __shared__ float s_mt[NCLS][TC], s_lmm[NCLS][TC];
    __shared__ float s_nred[NK * 33];     // padded norm tile (reused for sv)
    __shared__ int   s_last;

    const int t    = threadIdx.x;
    const int base = blockIdx.x * TC;

    // ---- tiny prep: labels sort + ratio tables + miu tables ----
    if (t < BATCH) s_lab[t] = labels[t];
    if (t < NCLS)  s_hist[t] = 0;
    if (t >= 64 && t < 64 + NK) {
        int k = t - 64, c = k >> 2, d = k & 3;
        float s2 = sigmas[c] * sigmas[c], t2 = tao[d] * tao[d];
        float inv = 1.f / (s2 + t2);
        s_rt[k] = t2 * inv; s_rs[k] = s2 * inv;
    }
    if (t >= 104 && t < 108) {
        int d = t - 104;
        float s = w1[0]*w1[0] + w1[1]*w1[1] + w1[2]*w1[2] + w1[3]*w1[3];
        s_w[d] = w1[d] * w1[d] / s;
    }
    if (t >= 128) {   // threads 128..255: one miu value each for s_lsm
        int k = t - 128, d = k >> 5, slot = k & 31, ff = slot >> 4, ci = slot & 15;
        s_lsm[d][slot] = lsig(miu[d * FCHW + ff * CHW + base + ci]);
    }
    if (t < 64) {
        int d = t >> 4, ci = t & 15;
        s_lsme[d][ci] = lsig(miu[d * FCHW + CHW + base + ci] + EPSV);
        s_miu0[d][ci] = miu[d * FCHW + base + ci];
    }
    __syncthreads();
    if (t < BATCH) atomicAdd(&s_hist[s_lab[t]], 1);
    __syncthreads();
    if (t == 0) {
        int p = 0;
        for (int c = 0; c < NCLS; c++) { s_start[c] = p; p += s_hist[c]; }
        s_start[NCLS] = p;
    }
    if (t < NCLS) s_inv[t] = 1.f / (Xw[t] + (float)s_hist[t]);
    __syncthreads();
    if (t < BATCH) {                 // stable rank within class
        int lab = s_lab[t], r = 0;
        for (int j = 0; j < t; j++) r += (s_lab[j] == lab);
        s_ord[s_start[lab] + r] = t;
    }
    __syncthreads();

    // ---- phase 1: warp g owns classes {g, g+8}; lanes = 32 (f,chw) slots ----
    const int slot = t & 31, g = t >> 5;          // g in [0,8)
    const int ff = slot >> 4, ci = slot & 15;
    const int idx = ff * CHW + base + ci;

    for (int c = g; c < NCLS; c += 8) {
        float s = 0.f;
        const int j1 = s_start[c + 1];
        for (int j = s_start[c]; j < j1; j++)
            s += xle[s_ord[j] * FCHW + idx];       // coalesced across lanes
        const float xb = (XLEs[c * FCHW + idx] + s) * s_inv[c];
        const float lx = lsig(xb);
#pragma unroll
        for (int d = 0; d < NDIR; d++) {
            float df = lx - s_lsm[d][slot];
            s_nred[(d * NCLS + c) * 33 + slot] = df * df;
        }
        if (ff) {   // means from x_bins[c, f=1, chw] = xb
            float lmag = lsig(xb + EPSV);
            float mm = 0.f, mt = 0.f;
#pragma unroll
            for (int d = 0; d < NDIR; d++) {
                float rt = s_rt[c * 4 + d], rs = s_rs[c * 4 + d], w = s_w[d];
                mm += __expf((rt * lmag + rs * s_lsme[d][ci]) * w);
                mt += (xb * rt + s_miu0[d][ci] * rs) * w;
            }
            s_mt[c][ci]  = mt;
            s_lmm[c][ci] = __logf(mm + EPSV);
        }
    }
    __syncthreads();

    // ---- norm partial -> global atomic (kills the serial tail reduce) ----
    if (t < NK) {
        float s = 0.f;
#pragma unroll
        for (int sl = 0; sl < 32; sl++) s += s_nred[t * 33 + sl];
        atomicAdd(&g_norm[t], s);
        __threadfence();            // order my REDG before my ctr arrival
    }

    // ---- phase 2: outputs; means via shared (broadcast, conflict-free) ----
    const int ci2 = t & 15, brow = t >> 4;        // brow in [0,16)
    const float w0  = weight[0] * weight[0];
    const float w1s = weight[1] * weight[1];
#pragma unroll
    for (int r = 0; r < 4; r++) {
        int b = r * 16 + brow;
        float x0  = xle[b * FCHW + base + ci2];            // L1-hot (phase 1 touched)
        float lx1 = __logf(xle[b * FCHW + CHW + base + ci2]);
        float best = 3.402823466e38f;
#pragma unroll
        for (int c = 0; c < NCLS; c++)
            best = fminf(best, fmaf(w0, fabsf(x0 - s_mt[c][ci2]),
                                    w1s * fabsf(lx1 - s_lmm[c][ci2])));
        out[b * CHW + base + ci2] = best;
    }

    // ---- loss in last-finished block ----
    __syncthreads();
    if (t == 0) s_last = (atomicAdd(&g_ctr, 1) == NBLK - 1) ? 1 : 0;
    __syncthreads();
    if (s_last) {
        if (t < NK) {
            float nrm = g_norm[t];                 // L2-current (never L1-cached here)
            int d = t / NCLS, c = t - d * NCLS;
            float t2 = tao[d] * tao[d], s2 = sigmas[c] * sigmas[c];
            float cnt = Xw[c] + (float)s_hist[c];
            float term1 = s2 / ((t2 + s2) * (t2 + s2));
            s_nred[t] = term1 * (s2 * nrm + 2.f * (float)CHW * (t2 * t2 - s2 * s2) / cnt);
            g_norm[t] = 0.f;                       // reset for next graph replay
        }
        __syncthreads();
        if (t < NDIR) {
            float s = 0.f;
#pragma unroll
            for (int c = 0; c < NCLS; c++) s += s_nred[t * NCLS + c];
            out[BATCH * CHW + t] = s * (1.f / NCLS);
        }
        if (t == 0) g_ctr = 0;                     // reset for next graph replay
    }
}

extern "C" void kernel_launch(void* const* d_in, const int* in_sizes, int n_in,
                              void* d_out, int out_size) {
    const float* xle    = (const float*)d_in[0];   // x_LE    (64,2,64,16,16)
    const int*   labels = (const int*)  d_in[1];   // labels  (64,)
    const float* w1     = (const float*)d_in[2];   // w1      (4,)
    // d_in[3] = w2 (unused: reference computes w2n from w1)
    const float* miu    = (const float*)d_in[4];   // miu     (4,2,64,16,16)
    const float* tao    = (const float*)d_in[5];   // tao     (4,)
    const float* weight = (const float*)d_in[6];   // weight  (2,)
    const float* sigmas = (const float*)d_in[7];   // sigmas  (10,)
    const float* XLEs   = (const float*)d_in[8];   // X_LEs   (10,2,64,16,16)
    const float* Xw     = (const float*)d_in[9];   // X_weights (10,1)
    float* out = (float*)d_out;                    // [x_out (64*16384) | loss (4)]

    k_all<<<NBLK, NTHR>>>(xle, XLEs, miu, labels, w1, tao, weight, sigmas, Xw, out);
}